// round 1
// baseline (speedup 1.0000x reference)
#include <cuda_runtime.h>
#include <cuda_bf16.h>

#define NODES  50000
#define NEDGES 600000
#define DD     128
#define BM     128
#define BN_EPS 1e-5f

// ---------------- scratch (no allocations allowed) ----------------
__device__ __align__(16) float g_agg[NODES * DD];   // 25.6 MB
__device__ __align__(16) float g_gX[NODES * DD];    // 25.6 MB
__device__ int   g_degout[NODES];
__device__ int   g_degin[NODES];
__device__ float g_sum[DD];
__device__ float g_sumsq[DD];
__device__ __align__(16) float g_scale[DD];
__device__ __align__(16) float g_bias[DD];

// ---------------- f32x2 helpers ----------------
__device__ __forceinline__ unsigned long long pk2(float lo, float hi) {
    unsigned long long r;
    asm("mov.b64 %0, {%1, %2};" : "=l"(r) : "f"(lo), "f"(hi));
    return r;
}
__device__ __forceinline__ void fma2(unsigned long long& d, unsigned long long a, unsigned long long b) {
    asm("fma.rn.f32x2 %0, %1, %2, %0;" : "+l"(d) : "l"(a), "l"(b));
}
__device__ __forceinline__ float2 upk2(unsigned long long v) {
    float2 f;
    asm("mov.b64 {%0, %1}, %2;" : "=f"(f.x), "=f"(f.y) : "l"(v));
    return f;
}

// ---------------- kernel 0: zero scratch ----------------
__global__ void k_init() {
    int i = blockIdx.x * blockDim.x + threadIdx.x;
    if (i < NODES * DD / 4) ((float4*)g_agg)[i] = make_float4(0.f, 0.f, 0.f, 0.f);
    if (i < NODES / 4) {
        ((int4*)g_degout)[i] = make_int4(0, 0, 0, 0);
        ((int4*)g_degin)[i]  = make_int4(0, 0, 0, 0);
    }
    if (i < DD) { g_sum[i] = 0.f; g_sumsq[i] = 0.f; }
}

// ---------------- kernel 1: degrees ----------------
__global__ void k_deg(const int* __restrict__ src, const int* __restrict__ dst) {
    int e = blockIdx.x * blockDim.x + threadIdx.x;
    if (e < NEDGES) {
        atomicAdd(&g_degout[src[e]], 1);
        atomicAdd(&g_degin[dst[e]], 1);
    }
}

// ---------------- kernel 2: edge scatter (warp per edge) ----------------
__global__ void k_scatter(const float* __restrict__ X,
                          const int* __restrict__ src, const int* __restrict__ dst) {
    int w    = (blockIdx.x * blockDim.x + threadIdx.x) >> 5;
    int lane = threadIdx.x & 31;
    if (w >= NEDGES) return;
    int s = __ldg(src + w);
    int d = __ldg(dst + w);
    float sc = rsqrtf((float)max(g_degout[s], 1));
    float4 v = __ldg((const float4*)(X + (size_t)s * DD) + lane);
    float* p = g_agg + (size_t)d * DD + lane * 4;
    asm volatile("red.global.add.v4.f32 [%0], {%1, %2, %3, %4};"
                 :: "l"(p), "f"(v.x * sc), "f"(v.y * sc), "f"(v.z * sc), "f"(v.w * sc)
                 : "memory");
}

// ---------------- kernel 3: fused dual GEMM + ReLU + BN partial stats ----------------
// gX = relu((agg*norm_dst) @ W) + relu(X @ Wres)
// Block: 256 threads, tile 128 rows x 128 cols, per-thread 8x8 via FFMA2.
// smem: Bs[128][128] (B matrix), As[128][128] (A tile, transposed [k][row]).
__global__ void __launch_bounds__(256, 1)
k_gemm(const float* __restrict__ X, const float* __restrict__ W, const float* __restrict__ Wres) {
    extern __shared__ float sm[];
    float* Bs = sm;           // 16384 floats
    float* As = sm + 16384;   // 16384 floats
    int tid = threadIdx.x;
    int tx = tid & 15, ty = tid >> 4;
    int m0 = blockIdx.x * BM;

    unsigned long long acc[8][4];
    float keep[8][8];

    // ---- phase 1: A = agg * norm_dst, B = W ----
    {
        const float4* W4 = (const float4*)W;
        float4* B4 = (float4*)Bs;
        #pragma unroll
        for (int j = tid; j < 4096; j += 256) B4[j] = __ldg(W4 + j);
    }
    #pragma unroll
    for (int j = tid; j < 4096; j += 256) {
        int r = j >> 5, q = j & 31;
        int m = m0 + r;
        float4 v = make_float4(0.f, 0.f, 0.f, 0.f);
        float scv = 0.f;
        if (m < NODES) {
            v = *((const float4*)(g_agg + (size_t)m * DD) + q);
            scv = rsqrtf((float)max(g_degin[m], 1));
        }
        int k = q * 4;
        As[(k + 0) * DD + r] = v.x * scv;
        As[(k + 1) * DD + r] = v.y * scv;
        As[(k + 2) * DD + r] = v.z * scv;
        As[(k + 3) * DD + r] = v.w * scv;
    }
    __syncthreads();

    #pragma unroll
    for (int i = 0; i < 8; i++)
        #pragma unroll
        for (int j = 0; j < 4; j++) acc[i][j] = 0ull;

    #pragma unroll 4
    for (int k = 0; k < 128; k++) {
        float4 a0 = *(const float4*)(As + k * DD + ty * 4);
        float4 a1 = *(const float4*)(As + k * DD + 64 + ty * 4);
        float4 b0 = *(const float4*)(Bs + k * DD + tx * 4);
        float4 b1 = *(const float4*)(Bs + k * DD + 64 + tx * 4);
        unsigned long long bp[4] = { pk2(b0.x, b0.y), pk2(b0.z, b0.w),
                                     pk2(b1.x, b1.y), pk2(b1.z, b1.w) };
        float av[8] = { a0.x, a0.y, a0.z, a0.w, a1.x, a1.y, a1.z, a1.w };
        #pragma unroll
        for (int i = 0; i < 8; i++) {
            unsigned long long ad = pk2(av[i], av[i]);
            #pragma unroll
            for (int j = 0; j < 4; j++) fma2(acc[i][j], ad, bp[j]);
        }
    }

    // relu into keep, reset acc
    #pragma unroll
    for (int i = 0; i < 8; i++)
        #pragma unroll
        for (int j = 0; j < 4; j++) {
            float2 f = upk2(acc[i][j]);
            keep[i][2 * j + 0] = fmaxf(f.x, 0.f);
            keep[i][2 * j + 1] = fmaxf(f.y, 0.f);
            acc[i][j] = 0ull;
        }
    __syncthreads();

    // ---- phase 2: A = X, B = Wres ----
    {
        const float4* W4 = (const float4*)Wres;
        float4* B4 = (float4*)Bs;
        #pragma unroll
        for (int j = tid; j < 4096; j += 256) B4[j] = __ldg(W4 + j);
    }
    #pragma unroll
    for (int j = tid; j < 4096; j += 256) {
        int r = j >> 5, q = j & 31;
        int m = m0 + r;
        float4 v = make_float4(0.f, 0.f, 0.f, 0.f);
        if (m < NODES) v = __ldg((const float4*)(X + (size_t)m * DD) + q);
        int k = q * 4;
        As[(k + 0) * DD + r] = v.x;
        As[(k + 1) * DD + r] = v.y;
        As[(k + 2) * DD + r] = v.z;
        As[(k + 3) * DD + r] = v.w;
    }
    __syncthreads();

    #pragma unroll 4
    for (int k = 0; k < 128; k++) {
        float4 a0 = *(const float4*)(As + k * DD + ty * 4);
        float4 a1 = *(const float4*)(As + k * DD + 64 + ty * 4);
        float4 b0 = *(const float4*)(Bs + k * DD + tx * 4);
        float4 b1 = *(const float4*)(Bs + k * DD + 64 + tx * 4);
        unsigned long long bp[4] = { pk2(b0.x, b0.y), pk2(b0.z, b0.w),
                                     pk2(b1.x, b1.y), pk2(b1.z, b1.w) };
        float av[8] = { a0.x, a0.y, a0.z, a0.w, a1.x, a1.y, a1.z, a1.w };
        #pragma unroll
        for (int i = 0; i < 8; i++) {
            unsigned long long ad = pk2(av[i], av[i]);
            #pragma unroll
            for (int j = 0; j < 4; j++) fma2(acc[i][j], ad, bp[j]);
        }
    }

    // final: keep += relu(acc2)
    #pragma unroll
    for (int i = 0; i < 8; i++)
        #pragma unroll
        for (int j = 0; j < 4; j++) {
            float2 f = upk2(acc[i][j]);
            keep[i][2 * j + 0] += fmaxf(f.x, 0.f);
            keep[i][2 * j + 1] += fmaxf(f.y, 0.f);
        }

    // store + per-thread column partials
    float cs[8], css[8];
    #pragma unroll
    for (int j = 0; j < 8; j++) { cs[j] = 0.f; css[j] = 0.f; }
    #pragma unroll
    for (int i = 0; i < 8; i++) {
        int r = (i < 4) ? (ty * 4 + i) : (64 + ty * 4 + (i - 4));
        int m = m0 + r;
        if (m < NODES) {
            float4 o0 = make_float4(keep[i][0], keep[i][1], keep[i][2], keep[i][3]);
            float4 o1 = make_float4(keep[i][4], keep[i][5], keep[i][6], keep[i][7]);
            *((float4*)(g_gX + (size_t)m * DD + tx * 4)) = o0;
            *((float4*)(g_gX + (size_t)m * DD + 64 + tx * 4)) = o1;
            #pragma unroll
            for (int j = 0; j < 8; j++) {
                cs[j] += keep[i][j];
                css[j] += keep[i][j] * keep[i][j];
            }
        }
    }

    // block-level column reduction in smem, then one global atomic per col
    __syncthreads();
    float* redsum = sm;
    float* redsq  = sm + 128;
    if (tid < 128) { redsum[tid] = 0.f; redsq[tid] = 0.f; }
    __syncthreads();
    #pragma unroll
    for (int j = 0; j < 8; j++) {
        int c = (j < 4) ? (tx * 4 + j) : (64 + tx * 4 + (j - 4));
        atomicAdd(&redsum[c], cs[j]);
        atomicAdd(&redsq[c], css[j]);
    }
    __syncthreads();
    if (tid < 128) {
        atomicAdd(&g_sum[tid], redsum[tid]);
        atomicAdd(&g_sumsq[tid], redsq[tid]);
    }
}

// ---------------- kernel 4: finalize BN affine coefficients ----------------
__global__ void k_finalize(const float* __restrict__ gamma, const float* __restrict__ beta) {
    int c = threadIdx.x;
    const float invN = 1.f / (float)NODES;
    float mean = g_sum[c] * invN;
    float var  = fmaxf(g_sumsq[c] * invN - mean * mean, 0.f);
    float inv  = rsqrtf(var + BN_EPS);
    float s = gamma[c] * inv;
    g_scale[c] = s;
    g_bias[c]  = beta[c] - s * mean;
}

// ---------------- kernel 5: apply BN ----------------
__global__ void k_bn(float* __restrict__ out) {
    int i = blockIdx.x * blockDim.x + threadIdx.x;
    if (i >= NODES * DD / 4) return;
    int c4 = i & 31;
    float4 sc = ((const float4*)g_scale)[c4];
    float4 bi = ((const float4*)g_bias)[c4];
    float4 v  = ((const float4*)g_gX)[i];
    float4 o;
    o.x = fmaf(v.x, sc.x, bi.x);
    o.y = fmaf(v.y, sc.y, bi.y);
    o.z = fmaf(v.z, sc.z, bi.z);
    o.w = fmaf(v.w, sc.w, bi.w);
    ((float4*)out)[i] = o;
}

// ---------------- launch ----------------
extern "C" void kernel_launch(void* const* d_in, const int* in_sizes, int n_in,
                              void* d_out, int out_size) {
    const float* X     = (const float*)d_in[0];
    const float* W     = (const float*)d_in[1];
    const float* Wres  = (const float*)d_in[2];
    const float* gamma = (const float*)d_in[3];
    const float* beta  = (const float*)d_in[4];
    const int*   src   = (const int*)d_in[5];
    const int*   dst   = (const int*)d_in[6];
    float* out = (float*)d_out;

    (void)in_sizes; (void)n_in; (void)out_size;

    cudaFuncSetAttribute(k_gemm, cudaFuncAttributeMaxDynamicSharedMemorySize, 131072);

    k_init<<<(NODES * DD / 4 + 255) / 256, 256>>>();
    k_deg<<<(NEDGES + 255) / 256, 256>>>(src, dst);
    k_scatter<<<(NEDGES * 32 + 255) / 256, 256>>>(X, src, dst);
    k_gemm<<<(NODES + BM - 1) / BM, 256, 131072>>>(X, W, Wres);
    k_finalize<<<1, DD>>>(gamma, beta);
    k_bn<<<(NODES * DD / 4 + 255) / 256, 256>>>(out);
}

// round 5
// speedup vs baseline: 1.3705x; 1.3705x over previous
#include <cuda_runtime.h>
#include <cuda_bf16.h>
#include <cstdint>

#define NODES  50000
#define NEDGES 600000
#define DD     128
#define BM     128
#define BN_EPS 1e-5f

// ---------------- scratch (no allocations allowed) ----------------
__device__ __align__(16) float g_agg[NODES * DD];   // 25.6 MB
__device__ __align__(16) float g_gX[NODES * DD];    // 25.6 MB
__device__ int   g_degout[NODES];
__device__ int   g_degin[NODES];
__device__ float g_sum[DD];
__device__ float g_sumsq[DD];
__device__ __align__(16) float g_scale[DD];
__device__ __align__(16) float g_bias[DD];

// ---------------- helpers ----------------
// cvt.rna.tf32.f32 writes a .b32 destination -> bind as "=r"
__device__ __forceinline__ uint32_t tf32u(float x) {
    uint32_t r;
    asm("cvt.rna.tf32.f32 %0, %1;" : "=r"(r) : "f"(x));
    return r;
}
__device__ __forceinline__ void split2(float x, float& hi, float& lo) {
    hi = __uint_as_float(tf32u(x));
    lo = __uint_as_float(tf32u(x - hi));
}
__device__ __forceinline__ void mma_tf32(float* d, const uint32_t* a, const uint32_t* b) {
    asm volatile("mma.sync.aligned.m16n8k8.row.col.f32.tf32.tf32.f32 "
        "{%0,%1,%2,%3}, {%4,%5,%6,%7}, {%8,%9}, {%0,%1,%2,%3};"
        : "+f"(d[0]), "+f"(d[1]), "+f"(d[2]), "+f"(d[3])
        : "r"(a[0]), "r"(a[1]), "r"(a[2]), "r"(a[3]), "r"(b[0]), "r"(b[1]));
}

// smem float offsets
#define F_AHI 0
#define F_ALO 4608       // 128*36
#define F_BHI 9216
#define F_BLO 13568      // 9216 + 32*136
#define SMEM_FLOATS 17920
#define SMEM_BYTES  (SMEM_FLOATS * 4)
#define APAD 36
#define BPAD 136

// ---------------- kernel 0: zero scratch ----------------
__global__ void k_init() {
    int i = blockIdx.x * blockDim.x + threadIdx.x;
    if (i < NODES * DD / 4) ((float4*)g_agg)[i] = make_float4(0.f, 0.f, 0.f, 0.f);
    if (i < NODES / 4) {
        ((int4*)g_degout)[i] = make_int4(0, 0, 0, 0);
        ((int4*)g_degin)[i]  = make_int4(0, 0, 0, 0);
    }
    if (i < DD) { g_sum[i] = 0.f; g_sumsq[i] = 0.f; }
}

// ---------------- kernel 1: degrees ----------------
__global__ void k_deg(const int* __restrict__ src, const int* __restrict__ dst) {
    int e = blockIdx.x * blockDim.x + threadIdx.x;
    if (e < NEDGES) {
        atomicAdd(&g_degout[src[e]], 1);
        atomicAdd(&g_degin[dst[e]], 1);
    }
}

// ---------------- kernel 2: edge scatter (warp per edge) ----------------
__global__ void k_scatter(const float* __restrict__ X,
                          const int* __restrict__ src, const int* __restrict__ dst) {
    int w    = (blockIdx.x * blockDim.x + threadIdx.x) >> 5;
    int lane = threadIdx.x & 31;
    if (w >= NEDGES) return;
    int s = __ldg(src + w);
    int d = __ldg(dst + w);
    float sc = rsqrtf((float)max(g_degout[s], 1));
    float4 v = __ldg((const float4*)(X + (size_t)s * DD) + lane);
    float* p = g_agg + (size_t)d * DD + lane * 4;
    asm volatile("red.global.add.v4.f32 [%0], {%1, %2, %3, %4};"
                 :: "l"(p), "f"(v.x * sc), "f"(v.y * sc), "f"(v.z * sc), "f"(v.w * sc)
                 : "memory");
}

// ---------------- one GEMM phase: acc += srcA[m0:m0+128, :] @ srcB (3xTF32) ----------------
__device__ __forceinline__ void run_phase(const float* __restrict__ srcA,
                                          const float* __restrict__ srcB,
                                          float* __restrict__ sm, int m0, int tid,
                                          float acc[4][4][4]) {
    float* As_hi = sm + F_AHI;
    float* As_lo = sm + F_ALO;
    float* Bs_hi = sm + F_BHI;
    float* Bs_lo = sm + F_BLO;
    const int lane = tid & 31, wid = tid >> 5;
    const int wm = (wid >> 2) * 64;        // warp row base: 0 or 64
    const int wn = (wid & 3) * 32;         // warp col base: 0,32,64,96
    const int gr = lane >> 2, kq = lane & 3;

    for (int kc = 0; kc < 4; kc++) {
        __syncthreads();
        // ---- stage A chunk [128 m][32 k] -> hi/lo ----
        #pragma unroll
        for (int it = 0; it < 4; it++) {
            int idx = tid + it * 256;
            int m = idx >> 3, k = (idx & 7) * 4;
            int gm = m0 + m;
            float4 v = make_float4(0.f, 0.f, 0.f, 0.f);
            if (gm < NODES) v = __ldg((const float4*)(srcA + (size_t)gm * DD + kc * 32 + k));
            float4 h, l;
            split2(v.x, h.x, l.x);
            split2(v.y, h.y, l.y);
            split2(v.z, h.z, l.z);
            split2(v.w, h.w, l.w);
            *(float4*)(As_hi + m * APAD + k) = h;
            *(float4*)(As_lo + m * APAD + k) = l;
        }
        // ---- stage B chunk [32 k][128 n] -> hi/lo ----
        #pragma unroll
        for (int it = 0; it < 4; it++) {
            int idx = tid + it * 256;
            int kr = idx >> 5, n = (idx & 31) * 4;
            float4 v = __ldg((const float4*)(srcB + (size_t)(kc * 32 + kr) * DD + n));
            float4 h, l;
            split2(v.x, h.x, l.x);
            split2(v.y, h.y, l.y);
            split2(v.z, h.z, l.z);
            split2(v.w, h.w, l.w);
            *(float4*)(Bs_hi + kr * BPAD + n) = h;
            *(float4*)(Bs_lo + kr * BPAD + n) = l;
        }
        __syncthreads();

        // ---- 4 x k8 sub-steps ----
        #pragma unroll
        for (int k8 = 0; k8 < 4; k8++) {
            int kk = k8 * 8;
            uint32_t ah[4][4], al[4][4], bh[4][2], bl[4][2];
            #pragma unroll
            for (int mt = 0; mt < 4; mt++) {
                int r = wm + mt * 16 + gr;
                const float* p = As_hi + r * APAD + kk + kq;
                const float* q = As_lo + r * APAD + kk + kq;
                ah[mt][0] = __float_as_uint(p[0]);
                ah[mt][1] = __float_as_uint(p[8 * APAD]);
                ah[mt][2] = __float_as_uint(p[4]);
                ah[mt][3] = __float_as_uint(p[8 * APAD + 4]);
                al[mt][0] = __float_as_uint(q[0]);
                al[mt][1] = __float_as_uint(q[8 * APAD]);
                al[mt][2] = __float_as_uint(q[4]);
                al[mt][3] = __float_as_uint(q[8 * APAD + 4]);
            }
            #pragma unroll
            for (int nt = 0; nt < 4; nt++) {
                int c = wn + nt * 8 + gr;
                const float* p = Bs_hi + (kk + kq) * BPAD + c;
                const float* q = Bs_lo + (kk + kq) * BPAD + c;
                bh[nt][0] = __float_as_uint(p[0]);
                bh[nt][1] = __float_as_uint(p[4 * BPAD]);
                bl[nt][0] = __float_as_uint(q[0]);
                bl[nt][1] = __float_as_uint(q[4 * BPAD]);
            }
            #pragma unroll
            for (int mt = 0; mt < 4; mt++)
                #pragma unroll
                for (int nt = 0; nt < 4; nt++) {
                    mma_tf32(acc[mt][nt], ah[mt], bh[nt]);
                    mma_tf32(acc[mt][nt], al[mt], bh[nt]);
                    mma_tf32(acc[mt][nt], ah[mt], bl[nt]);
                }
        }
    }
}

// ---------------- kernel 3: mma.sync tf32 dual GEMM + fused BN stats ----------------
// gX = relu((agg@W) * norm_dst) + relu(X@Wres); also accumulates g_sum/g_sumsq.
__global__ void __launch_bounds__(256, 1)
k_gemm_mma(const float* __restrict__ X, const float* __restrict__ W,
           const float* __restrict__ Wres) {
    extern __shared__ float sm[];
    const int tid = threadIdx.x;
    const int m0 = blockIdx.x * BM;
    const int lane = tid & 31, wid = tid >> 5;
    const int wm = (wid >> 2) * 64, wn = (wid & 3) * 32;
    const int gr = lane >> 2, kq = lane & 3;

    float acc[4][4][4];
    float keep[4][4][4];

    // ---- phase 1: residual X @ Wres ----
    #pragma unroll
    for (int mt = 0; mt < 4; mt++)
        #pragma unroll
        for (int nt = 0; nt < 4; nt++)
            #pragma unroll
            for (int q = 0; q < 4; q++) acc[mt][nt][q] = 0.f;
    run_phase(X, Wres, sm, m0, tid, acc);
    #pragma unroll
    for (int mt = 0; mt < 4; mt++)
        #pragma unroll
        for (int nt = 0; nt < 4; nt++)
            #pragma unroll
            for (int q = 0; q < 4; q++) {
                keep[mt][nt][q] = fmaxf(acc[mt][nt][q], 0.f);
                acc[mt][nt][q] = 0.f;
            }

    // ---- phase 2: conv agg @ W ----
    run_phase(g_agg, W, sm, m0, tid, acc);

    // ---- epilogue: combine, store, column stats ----
    float cs[8], cq[8];
    #pragma unroll
    for (int j = 0; j < 8; j++) { cs[j] = 0.f; cq[j] = 0.f; }

    #pragma unroll
    for (int mt = 0; mt < 4; mt++) {
        int r0 = m0 + wm + mt * 16 + gr;
        int r1 = r0 + 8;
        float s0 = (r0 < NODES) ? rsqrtf((float)max(g_degin[r0], 1)) : 0.f;
        float s1 = (r1 < NODES) ? rsqrtf((float)max(g_degin[r1], 1)) : 0.f;
        #pragma unroll
        for (int nt = 0; nt < 4; nt++) {
            float v0 = keep[mt][nt][0] + fmaxf(acc[mt][nt][0] * s0, 0.f);
            float v1 = keep[mt][nt][1] + fmaxf(acc[mt][nt][1] * s0, 0.f);
            float v2 = keep[mt][nt][2] + fmaxf(acc[mt][nt][2] * s1, 0.f);
            float v3 = keep[mt][nt][3] + fmaxf(acc[mt][nt][3] * s1, 0.f);
            int c = wn + nt * 8 + kq * 2;
            if (r0 < NODES) *(float2*)(g_gX + (size_t)r0 * DD + c) = make_float2(v0, v1);
            if (r1 < NODES) *(float2*)(g_gX + (size_t)r1 * DD + c) = make_float2(v2, v3);
            cs[2 * nt + 0] += v0 + v2;
            cs[2 * nt + 1] += v1 + v3;
            cq[2 * nt + 0] += v0 * v0 + v2 * v2;
            cq[2 * nt + 1] += v1 * v1 + v3 * v3;
        }
    }

    // reduce across the 8 lanes sharing each column (gr varies, kq fixed)
    #pragma unroll
    for (int j = 0; j < 8; j++) {
        #pragma unroll
        for (int off = 16; off >= 4; off >>= 1) {
            cs[j] += __shfl_xor_sync(0xFFFFFFFF, cs[j], off);
            cq[j] += __shfl_xor_sync(0xFFFFFFFF, cq[j], off);
        }
    }

    __syncthreads();
    float* redsum = sm;
    float* redsq  = sm + 128;
    if (tid < 128) { redsum[tid] = 0.f; redsq[tid] = 0.f; }
    __syncthreads();
    if (gr == 0) {  // one lane per (warp, kq)
        #pragma unroll
        for (int j = 0; j < 8; j++) {
            int c = wn + (j >> 1) * 8 + kq * 2 + (j & 1);
            atomicAdd(&redsum[c], cs[j]);
            atomicAdd(&redsq[c], cq[j]);
        }
    }
    __syncthreads();
    if (tid < 128) {
        atomicAdd(&g_sum[tid], redsum[tid]);
        atomicAdd(&g_sumsq[tid], redsq[tid]);
    }
}

// ---------------- kernel 4: finalize BN affine coefficients ----------------
__global__ void k_finalize(const float* __restrict__ gamma, const float* __restrict__ beta) {
    int c = threadIdx.x;
    const float invN = 1.f / (float)NODES;
    float mean = g_sum[c] * invN;
    float var  = fmaxf(g_sumsq[c] * invN - mean * mean, 0.f);
    float inv  = rsqrtf(var + BN_EPS);
    float s = gamma[c] * inv;
    g_scale[c] = s;
    g_bias[c]  = beta[c] - s * mean;
}

// ---------------- kernel 5: apply BN ----------------
__global__ void k_bn(float* __restrict__ out) {
    int i = blockIdx.x * blockDim.x + threadIdx.x;
    if (i >= NODES * DD / 4) return;
    int c4 = i & 31;
    float4 sc = ((const float4*)g_scale)[c4];
    float4 bi = ((const float4*)g_bias)[c4];
    float4 v  = ((const float4*)g_gX)[i];
    float4 o;
    o.x = fmaf(v.x, sc.x, bi.x);
    o.y = fmaf(v.y, sc.y, bi.y);
    o.z = fmaf(v.z, sc.z, bi.z);
    o.w = fmaf(v.w, sc.w, bi.w);
    ((float4*)out)[i] = o;
}

// ---------------- launch ----------------
extern "C" void kernel_launch(void* const* d_in, const int* in_sizes, int n_in,
                              void* d_out, int out_size) {
    const float* X     = (const float*)d_in[0];
    const float* W     = (const float*)d_in[1];
    const float* Wres  = (const float*)d_in[2];
    const float* gamma = (const float*)d_in[3];
    const float* beta  = (const float*)d_in[4];
    const int*   src   = (const int*)d_in[5];
    const int*   dst   = (const int*)d_in[6];
    float* out = (float*)d_out;

    (void)in_sizes; (void)n_in; (void)out_size;

    cudaFuncSetAttribute(k_gemm_mma, cudaFuncAttributeMaxDynamicSharedMemorySize, SMEM_BYTES);

    k_init<<<(NODES * DD / 4 + 255) / 256, 256>>>();
    k_deg<<<(NEDGES + 255) / 256, 256>>>(src, dst);
    k_scatter<<<(NEDGES * 32 + 255) / 256, 256>>>(X, src, dst);
    k_gemm_mma<<<(NODES + BM - 1) / BM, 256, SMEM_BYTES>>>(X, W, Wres);
    k_finalize<<<1, DD>>>(gamma, beta);
    k_bn<<<(NODES * DD / 4 + 255) / 256, 256>>>(out);
}

// round 6
// speedup vs baseline: 1.4178x; 1.0345x over previous
#include <cuda_runtime.h>
#include <cuda_bf16.h>
#include <cstdint>

#define NODES  50000
#define NEDGES 600000
#define DD     128
#define BM     128
#define BN_EPS 1e-5f

// ---------------- scratch (no allocations allowed) ----------------
__device__ __align__(16) float g_agg[NODES * DD];   // 25.6 MB
__device__ __align__(16) float g_gX[NODES * DD];    // 25.6 MB
__device__ int   g_degout[NODES];
__device__ int   g_degin[NODES];
__device__ float g_sum[DD];
__device__ float g_sumsq[DD];
__device__ __align__(16) float g_scale[DD];
__device__ __align__(16) float g_bias[DD];

// ---------------- helpers ----------------
// cvt.rna.tf32.f32 writes a .b32 destination -> bind as "=r"
__device__ __forceinline__ uint32_t tf32u(float x) {
    uint32_t r;
    asm("cvt.rna.tf32.f32 %0, %1;" : "=r"(r) : "f"(x));
    return r;
}
__device__ __forceinline__ void split2(float x, float& hi, float& lo) {
    hi = __uint_as_float(tf32u(x));
    lo = __uint_as_float(tf32u(x - hi));
}
__device__ __forceinline__ void mma_tf32(float* d, const uint32_t* a, const uint32_t* b) {
    asm volatile("mma.sync.aligned.m16n8k8.row.col.f32.tf32.tf32.f32 "
        "{%0,%1,%2,%3}, {%4,%5,%6,%7}, {%8,%9}, {%0,%1,%2,%3};"
        : "+f"(d[0]), "+f"(d[1]), "+f"(d[2]), "+f"(d[3])
        : "r"(a[0]), "r"(a[1]), "r"(a[2]), "r"(a[3]), "r"(b[0]), "r"(b[1]));
}

// smem float offsets (B full-resident, A double-buffered)
#define APAD 36
#define BPAD 136
#define F_BHI 0
#define F_BLO 17408            // 128*136
#define F_A0  34816            // buffer 0 hi; +4608 = lo; buffer stride 9216
#define ABUF_STRIDE 9216
#define SMEM_FLOATS 53248      // 34816 + 2*9216
#define SMEM_BYTES  (SMEM_FLOATS * 4)   // 212992

// ---------------- kernel 0: zero scratch ----------------
__global__ void k_init() {
    int i = blockIdx.x * blockDim.x + threadIdx.x;
    if (i < NODES * DD / 4) ((float4*)g_agg)[i] = make_float4(0.f, 0.f, 0.f, 0.f);
    if (i < NODES / 4) {
        ((int4*)g_degout)[i] = make_int4(0, 0, 0, 0);
        ((int4*)g_degin)[i]  = make_int4(0, 0, 0, 0);
    }
    if (i < DD) { g_sum[i] = 0.f; g_sumsq[i] = 0.f; }
}

// ---------------- kernel 1: degrees ----------------
__global__ void k_deg(const int* __restrict__ src, const int* __restrict__ dst) {
    int e = blockIdx.x * blockDim.x + threadIdx.x;
    if (e < NEDGES) {
        atomicAdd(&g_degout[src[e]], 1);
        atomicAdd(&g_degin[dst[e]], 1);
    }
}

// ---------------- kernel 2: edge scatter (warp per edge) ----------------
__global__ void k_scatter(const float* __restrict__ X,
                          const int* __restrict__ src, const int* __restrict__ dst) {
    int w    = (blockIdx.x * blockDim.x + threadIdx.x) >> 5;
    int lane = threadIdx.x & 31;
    if (w >= NEDGES) return;
    int s = __ldg(src + w);
    int d = __ldg(dst + w);
    float sc = rsqrtf((float)max(g_degout[s], 1));
    float4 v = __ldg((const float4*)(X + (size_t)s * DD) + lane);
    float* p = g_agg + (size_t)d * DD + lane * 4;
    asm volatile("red.global.add.v4.f32 [%0], {%1, %2, %3, %4};"
                 :: "l"(p), "f"(v.x * sc), "f"(v.y * sc), "f"(v.z * sc), "f"(v.w * sc)
                 : "memory");
}

// ---------------- GEMM staging helpers ----------------
// Stage full B matrix [128 k][128 n] -> hi/lo (once per phase; B is L2-hot)
__device__ __forceinline__ void stageB(const float* __restrict__ srcB,
                                       float* __restrict__ bhi, float* __restrict__ blo,
                                       int tid) {
    #pragma unroll
    for (int it = 0; it < 16; it++) {
        int idx = tid + it * 256;           // 4096 float4s = 128x128
        int kr = idx >> 5, n = (idx & 31) * 4;
        float4 v = __ldg((const float4*)(srcB + (size_t)kr * DD + n));
        float4 h, l;
        split2(v.x, h.x, l.x);
        split2(v.y, h.y, l.y);
        split2(v.z, h.z, l.z);
        split2(v.w, h.w, l.w);
        *(float4*)(bhi + kr * BPAD + n) = h;
        *(float4*)(blo + kr * BPAD + n) = l;
    }
}

// Prefetch one A chunk [128 m][32 k] into registers
__device__ __forceinline__ void ldA(const float* __restrict__ srcA, int m0, int tid,
                                    int kc, float4* a_pf) {
    #pragma unroll
    for (int it = 0; it < 4; it++) {
        int idx = tid + it * 256;
        int m = idx >> 3, k = (idx & 7) * 4;
        int gm = m0 + m;
        a_pf[it] = (gm < NODES)
                 ? __ldg((const float4*)(srcA + (size_t)gm * DD + kc * 32 + k))
                 : make_float4(0.f, 0.f, 0.f, 0.f);
    }
}

// Split prefetched A chunk into smem hi/lo
__device__ __forceinline__ void stA(float* __restrict__ ahi, float* __restrict__ alo,
                                    int tid, const float4* a_pf) {
    #pragma unroll
    for (int it = 0; it < 4; it++) {
        int idx = tid + it * 256;
        int m = idx >> 3, k = (idx & 7) * 4;
        float4 v = a_pf[it], h, l;
        split2(v.x, h.x, l.x);
        split2(v.y, h.y, l.y);
        split2(v.z, h.z, l.z);
        split2(v.w, h.w, l.w);
        *(float4*)(ahi + m * APAD + k) = h;
        *(float4*)(alo + m * APAD + k) = l;
    }
}

// ---------------- one GEMM phase: acc += srcA[m0:m0+128, :] @ srcB (3xTF32) ----------------
// Software-pipelined: full-B resident, A double-buffered with register prefetch.
__device__ __forceinline__ void run_phase(const float* __restrict__ srcA,
                                          const float* __restrict__ srcB,
                                          float* __restrict__ sm, int m0, int tid,
                                          float acc[4][4][4]) {
    float* Bhi = sm + F_BHI;
    float* Blo = sm + F_BLO;
    const int lane = tid & 31, wid = tid >> 5;
    const int wm = (wid >> 2) * 64;        // warp row base: 0 or 64
    const int wn = (wid & 3) * 32;         // warp col base: 0,32,64,96
    const int gr = lane >> 2, kq = lane & 3;

    stageB(srcB, Bhi, Blo, tid);

    float4 a_pf[4];
    ldA(srcA, m0, tid, 0, a_pf);

    #pragma unroll 1
    for (int kc = 0; kc < 4; kc++) {
        float* Ahi = sm + F_A0 + (kc & 1) * ABUF_STRIDE;
        float* Alo = Ahi + 4608;
        stA(Ahi, Alo, tid, a_pf);
        __syncthreads();
        if (kc < 3) ldA(srcA, m0, tid, kc + 1, a_pf);   // overlaps MMA below

        #pragma unroll
        for (int k8 = 0; k8 < 4; k8++) {
            int kk = k8 * 8;
            int bk = kc * 32 + kk + kq;
            uint32_t ah[4][4], al[4][4], bh[4][2], bl[4][2];
            #pragma unroll
            for (int mt = 0; mt < 4; mt++) {
                int r = wm + mt * 16 + gr;
                const float* p = Ahi + r * APAD + kk + kq;
                const float* q = Alo + r * APAD + kk + kq;
                ah[mt][0] = __float_as_uint(p[0]);
                ah[mt][1] = __float_as_uint(p[8 * APAD]);
                ah[mt][2] = __float_as_uint(p[4]);
                ah[mt][3] = __float_as_uint(p[8 * APAD + 4]);
                al[mt][0] = __float_as_uint(q[0]);
                al[mt][1] = __float_as_uint(q[8 * APAD]);
                al[mt][2] = __float_as_uint(q[4]);
                al[mt][3] = __float_as_uint(q[8 * APAD + 4]);
            }
            #pragma unroll
            for (int nt = 0; nt < 4; nt++) {
                int c = wn + nt * 8 + gr;
                const float* p = Bhi + bk * BPAD + c;
                const float* q = Blo + bk * BPAD + c;
                bh[nt][0] = __float_as_uint(p[0]);
                bh[nt][1] = __float_as_uint(p[4 * BPAD]);
                bl[nt][0] = __float_as_uint(q[0]);
                bl[nt][1] = __float_as_uint(q[4 * BPAD]);
            }
            #pragma unroll
            for (int mt = 0; mt < 4; mt++)
                #pragma unroll
                for (int nt = 0; nt < 4; nt++) {
                    mma_tf32(acc[mt][nt], ah[mt], bh[nt]);
                    mma_tf32(acc[mt][nt], al[mt], bh[nt]);
                    mma_tf32(acc[mt][nt], ah[mt], bl[nt]);
                }
        }
    }
    __syncthreads();   // protect B region before next phase overwrites it
}

// ---------------- kernel 3: mma.sync tf32 dual GEMM + fused BN stats ----------------
// gX = relu((agg@W) * norm_dst) + relu(X@Wres); also accumulates g_sum/g_sumsq.
__global__ void __launch_bounds__(256, 1)
k_gemm_mma(const float* __restrict__ X, const float* __restrict__ W,
           const float* __restrict__ Wres) {
    extern __shared__ float sm[];
    const int tid = threadIdx.x;
    const int m0 = blockIdx.x * BM;
    const int lane = tid & 31, wid = tid >> 5;
    const int wm = (wid >> 2) * 64, wn = (wid & 3) * 32;
    const int gr = lane >> 2, kq = lane & 3;

    float acc[4][4][4];
    float keep[4][4][4];

    // ---- phase 1: residual X @ Wres ----
    #pragma unroll
    for (int mt = 0; mt < 4; mt++)
        #pragma unroll
        for (int nt = 0; nt < 4; nt++)
            #pragma unroll
            for (int q = 0; q < 4; q++) acc[mt][nt][q] = 0.f;
    run_phase(X, Wres, sm, m0, tid, acc);
    #pragma unroll
    for (int mt = 0; mt < 4; mt++)
        #pragma unroll
        for (int nt = 0; nt < 4; nt++)
            #pragma unroll
            for (int q = 0; q < 4; q++) {
                keep[mt][nt][q] = fmaxf(acc[mt][nt][q], 0.f);
                acc[mt][nt][q] = 0.f;
            }

    // ---- phase 2: conv agg @ W ----
    run_phase(g_agg, W, sm, m0, tid, acc);

    // ---- epilogue: combine, store, column stats ----
    float cs[8], cq[8];
    #pragma unroll
    for (int j = 0; j < 8; j++) { cs[j] = 0.f; cq[j] = 0.f; }

    #pragma unroll
    for (int mt = 0; mt < 4; mt++) {
        int r0 = m0 + wm + mt * 16 + gr;
        int r1 = r0 + 8;
        float s0 = (r0 < NODES) ? rsqrtf((float)max(g_degin[r0], 1)) : 0.f;
        float s1 = (r1 < NODES) ? rsqrtf((float)max(g_degin[r1], 1)) : 0.f;
        #pragma unroll
        for (int nt = 0; nt < 4; nt++) {
            float v0 = keep[mt][nt][0] + fmaxf(acc[mt][nt][0] * s0, 0.f);
            float v1 = keep[mt][nt][1] + fmaxf(acc[mt][nt][1] * s0, 0.f);
            float v2 = keep[mt][nt][2] + fmaxf(acc[mt][nt][2] * s1, 0.f);
            float v3 = keep[mt][nt][3] + fmaxf(acc[mt][nt][3] * s1, 0.f);
            int c = wn + nt * 8 + kq * 2;
            if (r0 < NODES) *(float2*)(g_gX + (size_t)r0 * DD + c) = make_float2(v0, v1);
            if (r1 < NODES) *(float2*)(g_gX + (size_t)r1 * DD + c) = make_float2(v2, v3);
            cs[2 * nt + 0] += v0 + v2;
            cs[2 * nt + 1] += v1 + v3;
            cq[2 * nt + 0] += v0 * v0 + v2 * v2;
            cq[2 * nt + 1] += v1 * v1 + v3 * v3;
        }
    }

    // reduce across the 8 lanes sharing each column (gr varies, kq fixed)
    #pragma unroll
    for (int j = 0; j < 8; j++) {
        #pragma unroll
        for (int off = 16; off >= 4; off >>= 1) {
            cs[j] += __shfl_xor_sync(0xFFFFFFFF, cs[j], off);
            cq[j] += __shfl_xor_sync(0xFFFFFFFF, cq[j], off);
        }
    }

    __syncthreads();
    float* redsum = sm;
    float* redsq  = sm + 128;
    if (tid < 128) { redsum[tid] = 0.f; redsq[tid] = 0.f; }
    __syncthreads();
    if (gr == 0) {  // one lane per (warp, kq)
        #pragma unroll
        for (int j = 0; j < 8; j++) {
            int c = wn + (j >> 1) * 8 + kq * 2 + (j & 1);
            atomicAdd(&redsum[c], cs[j]);
            atomicAdd(&redsq[c], cq[j]);
        }
    }
    __syncthreads();
    if (tid < 128) {
        atomicAdd(&g_sum[tid], redsum[tid]);
        atomicAdd(&g_sumsq[tid], redsq[tid]);
    }
}

// ---------------- kernel 4: finalize BN affine coefficients ----------------
__global__ void k_finalize(const float* __restrict__ gamma, const float* __restrict__ beta) {
    int c = threadIdx.x;
    const float invN = 1.f / (float)NODES;
    float mean = g_sum[c] * invN;
    float var  = fmaxf(g_sumsq[c] * invN - mean * mean, 0.f);
    float inv  = rsqrtf(var + BN_EPS);
    float s = gamma[c] * inv;
    g_scale[c] = s;
    g_bias[c]  = beta[c] - s * mean;
}

// ---------------- kernel 5: apply BN ----------------
__global__ void k_bn(float* __restrict__ out) {
    int i = blockIdx.x * blockDim.x + threadIdx.x;
    if (i >= NODES * DD / 4) return;
    int c4 = i & 31;
    float4 sc = ((const float4*)g_scale)[c4];
    float4 bi = ((const float4*)g_bias)[c4];
    float4 v  = ((const float4*)g_gX)[i];
    float4 o;
    o.x = fmaf(v.x, sc.x, bi.x);
    o.y = fmaf(v.y, sc.y, bi.y);
    o.z = fmaf(v.z, sc.z, bi.z);
    o.w = fmaf(v.w, sc.w, bi.w);
    ((float4*)out)[i] = o;
}

// ---------------- launch ----------------
extern "C" void kernel_launch(void* const* d_in, const int* in_sizes, int n_in,
                              void* d_out, int out_size) {
    const float* X     = (const float*)d_in[0];
    const float* W     = (const float*)d_in[1];
    const float* Wres  = (const float*)d_in[2];
    const float* gamma = (const float*)d_in[3];
    const float* beta  = (const float*)d_in[4];
    const int*   src   = (const int*)d_in[5];
    const int*   dst   = (const int*)d_in[6];
    float* out = (float*)d_out;

    (void)in_sizes; (void)n_in; (void)out_size;

    cudaFuncSetAttribute(k_gemm_mma, cudaFuncAttributeMaxDynamicSharedMemorySize, SMEM_BYTES);

    k_init<<<(NODES * DD / 4 + 255) / 256, 256>>>();
    k_deg<<<(NEDGES + 255) / 256, 256>>>(src, dst);
    k_scatter<<<(NEDGES * 32 + 255) / 256, 256>>>(X, src, dst);
    k_gemm_mma<<<(NODES + BM - 1) / BM, 256, SMEM_BYTES>>>(X, W, Wres);
    k_finalize<<<1, DD>>>(gamma, beta);
    k_bn<<<(NODES * DD / 4 + 255) / 256, 256>>>(out);
}

// round 7
// speedup vs baseline: 1.5963x; 1.1259x over previous
#include <cuda_runtime.h>
#include <cuda_bf16.h>
#include <cstdint>

#define NODES  50000
#define NEDGES 600000
#define DD     128
#define BM     128
#define BN_EPS 1e-5f

// ---------------- scratch (no allocations allowed) ----------------
__device__ __align__(16) float g_agg[NODES * DD];   // 25.6 MB
__device__ __align__(16) float g_gX[NODES * DD];    // 25.6 MB
__device__ int   g_degout[NODES];
__device__ int   g_degin[NODES];
__device__ float g_sum[DD];
__device__ float g_sumsq[DD];
__device__ __align__(16) float g_scale[DD];
__device__ __align__(16) float g_bias[DD];

// ---------------- bf16 split helpers (integer RNE, no cvt pipe) ----------------
// round x to bf16 (kept as f32 with low 16 bits zero); returns bits (low16==0)
__device__ __forceinline__ uint32_t bf16_hi_bits(float x) {
    uint32_t b = __float_as_uint(x);
    return (b + 0x7FFFu + ((b >> 16) & 1u)) & 0xFFFF0000u;
}
// split pair (ve = k-even, vo = k-odd) into packed bf16x2 hi word + lo word
__device__ __forceinline__ void bpack(float ve, float vo, uint32_t& whi, uint32_t& wlo) {
    uint32_t he = bf16_hi_bits(ve), ho = bf16_hi_bits(vo);
    float re = ve - __uint_as_float(he);
    float ro = vo - __uint_as_float(ho);
    uint32_t le = bf16_hi_bits(re), lo = bf16_hi_bits(ro);
    whi = ho | (he >> 16);   // low half = k-even
    wlo = lo | (le >> 16);
}

__device__ __forceinline__ void mma_bf16(float* d, const uint32_t* a, const uint32_t* b) {
    asm volatile("mma.sync.aligned.m16n8k16.row.col.f32.bf16.bf16.f32 "
        "{%0,%1,%2,%3}, {%4,%5,%6,%7}, {%8,%9}, {%0,%1,%2,%3};"
        : "+f"(d[0]), "+f"(d[1]), "+f"(d[2]), "+f"(d[3])
        : "r"(a[0]), "r"(a[1]), "r"(a[2]), "r"(a[3]), "r"(b[0]), "r"(b[1]));
}

// smem word (uint32) offsets. B full-resident [64 k2][136], A double-buffered [128][20].
#define BPADW 136
#define APADW 20
#define W_BHI 0
#define W_BLO 8704             // 64*136
#define W_A0  17408            // buffer stride 5120 (hi 2560 + lo 2560)
#define ABUF_W 5120
#define SMEM_WORDS 27648       // 17408 + 2*5120
#define SMEM_BYTES (SMEM_WORDS * 4)   // 110592

// ---------------- kernel 0: zero scratch ----------------
__global__ void k_init() {
    int i = blockIdx.x * blockDim.x + threadIdx.x;
    if (i < NODES * DD / 4) ((float4*)g_agg)[i] = make_float4(0.f, 0.f, 0.f, 0.f);
    if (i < NODES / 4) {
        ((int4*)g_degout)[i] = make_int4(0, 0, 0, 0);
        ((int4*)g_degin)[i]  = make_int4(0, 0, 0, 0);
    }
    if (i < DD) { g_sum[i] = 0.f; g_sumsq[i] = 0.f; }
}

// ---------------- kernel 1: degrees ----------------
__global__ void k_deg(const int* __restrict__ src, const int* __restrict__ dst) {
    int e = blockIdx.x * blockDim.x + threadIdx.x;
    if (e < NEDGES) {
        atomicAdd(&g_degout[src[e]], 1);
        atomicAdd(&g_degin[dst[e]], 1);
    }
}

// ---------------- kernel 2: edge scatter (warp per edge) ----------------
__global__ void k_scatter(const float* __restrict__ X,
                          const int* __restrict__ src, const int* __restrict__ dst) {
    int w    = (blockIdx.x * blockDim.x + threadIdx.x) >> 5;
    int lane = threadIdx.x & 31;
    if (w >= NEDGES) return;
    int s = __ldg(src + w);
    int d = __ldg(dst + w);
    float sc = rsqrtf((float)max(g_degout[s], 1));
    float4 v = __ldg((const float4*)(X + (size_t)s * DD) + lane);
    float* p = g_agg + (size_t)d * DD + lane * 4;
    asm volatile("red.global.add.v4.f32 [%0], {%1, %2, %3, %4};"
                 :: "l"(p), "f"(v.x * sc), "f"(v.y * sc), "f"(v.z * sc), "f"(v.w * sc)
                 : "memory");
}

// ---------------- GEMM staging ----------------
// Stage full B [128 k][128 n] -> bf16x2 words [64 k2][136]
__device__ __forceinline__ void stageB(const float* __restrict__ srcB,
                                       uint32_t* __restrict__ bhi,
                                       uint32_t* __restrict__ blo, int tid) {
    #pragma unroll
    for (int it = 0; it < 8; it++) {
        int idx = tid + it * 256;          // 2048 = 64 k2-rows x 32 n4
        int k2 = idx >> 5, n = (idx & 31) * 4;
        float4 f0 = __ldg((const float4*)(srcB + (size_t)(2 * k2)     * DD + n));
        float4 f1 = __ldg((const float4*)(srcB + (size_t)(2 * k2 + 1) * DD + n));
        uint32_t h0, l0, h1, l1, h2, l2, h3, l3;
        bpack(f0.x, f1.x, h0, l0);
        bpack(f0.y, f1.y, h1, l1);
        bpack(f0.z, f1.z, h2, l2);
        bpack(f0.w, f1.w, h3, l3);
        uint32_t* ph = bhi + k2 * BPADW + n;
        uint32_t* pl = blo + k2 * BPADW + n;
        ph[0] = h0; ph[1] = h1; ph[2] = h2; ph[3] = h3;
        pl[0] = l0; pl[1] = l1; pl[2] = l2; pl[3] = l3;
    }
}

// Prefetch one A chunk [128 m][32 k] into registers (8 floats per idx)
__device__ __forceinline__ void ldA(const float* __restrict__ srcA, int m0, int tid,
                                    int kc, float4* a_pf) {
    #pragma unroll
    for (int it = 0; it < 2; it++) {
        int idx = tid + it * 256;          // 512 = 128 m x 4 kw4
        int m = idx >> 2, kw4 = idx & 3;
        int gm = m0 + m;
        int k = kc * 32 + kw4 * 8;
        if (gm < NODES) {
            a_pf[it * 2 + 0] = __ldg((const float4*)(srcA + (size_t)gm * DD + k));
            a_pf[it * 2 + 1] = __ldg((const float4*)(srcA + (size_t)gm * DD + k + 4));
        } else {
            a_pf[it * 2 + 0] = make_float4(0.f, 0.f, 0.f, 0.f);
            a_pf[it * 2 + 1] = make_float4(0.f, 0.f, 0.f, 0.f);
        }
    }
}

// Split prefetched A chunk into smem word arrays [128][20]
__device__ __forceinline__ void stA(uint32_t* __restrict__ ahi, uint32_t* __restrict__ alo,
                                    int tid, const float4* a_pf) {
    #pragma unroll
    for (int it = 0; it < 2; it++) {
        int idx = tid + it * 256;
        int m = idx >> 2, kw4 = idx & 3;
        float4 f0 = a_pf[it * 2 + 0], f1 = a_pf[it * 2 + 1];
        uint32_t h0, l0, h1, l1, h2, l2, h3, l3;
        bpack(f0.x, f0.y, h0, l0);
        bpack(f0.z, f0.w, h1, l1);
        bpack(f1.x, f1.y, h2, l2);
        bpack(f1.z, f1.w, h3, l3);
        uint32_t* ph = ahi + m * APADW + kw4 * 4;
        uint32_t* pl = alo + m * APADW + kw4 * 4;
        ph[0] = h0; ph[1] = h1; ph[2] = h2; ph[3] = h3;
        pl[0] = l0; pl[1] = l1; pl[2] = l2; pl[3] = l3;
    }
}

// ---------------- one GEMM phase: acc += srcA[m0:m0+128, :] @ srcB (3xBF16) ----------------
__device__ __forceinline__ void run_phase(const float* __restrict__ srcA,
                                          const float* __restrict__ srcB,
                                          uint32_t* __restrict__ smw, int m0, int tid,
                                          float acc[4][4][4]) {
    uint32_t* Bhi = smw + W_BHI;
    uint32_t* Blo = smw + W_BLO;
    const int lane = tid & 31, wid = tid >> 5;
    const int wm = (wid >> 2) * 64;        // warp row base: 0 or 64
    const int wn = (wid & 3) * 32;         // warp col base: 0,32,64,96
    const int gr = lane >> 2, kq = lane & 3;

    stageB(srcB, Bhi, Blo, tid);

    float4 a_pf[4];
    ldA(srcA, m0, tid, 0, a_pf);

    #pragma unroll 1
    for (int kc = 0; kc < 4; kc++) {
        uint32_t* Ahi = smw + W_A0 + (kc & 1) * ABUF_W;
        uint32_t* Alo = Ahi + 2560;
        stA(Ahi, Alo, tid, a_pf);
        __syncthreads();
        if (kc < 3) ldA(srcA, m0, tid, kc + 1, a_pf);   // overlaps MMAs below

        #pragma unroll
        for (int ls = 0; ls < 2; ls++) {               // two k16-steps per 32-k chunk
            int ak2 = ls * 8;                          // A word col base (chunk-local)
            int bk2 = kc * 16 + ls * 8;                // B word row base (global)
            uint32_t ah[4][4], al[4][4], bh[4][2], bl[4][2];
            #pragma unroll
            for (int mt = 0; mt < 4; mt++) {
                int r = wm + mt * 16 + gr;
                const uint32_t* p = Ahi + r * APADW + ak2 + kq;
                const uint32_t* q = Alo + r * APADW + ak2 + kq;
                ah[mt][0] = p[0];
                ah[mt][1] = p[8 * APADW];
                ah[mt][2] = p[4];
                ah[mt][3] = p[8 * APADW + 4];
                al[mt][0] = q[0];
                al[mt][1] = q[8 * APADW];
                al[mt][2] = q[4];
                al[mt][3] = q[8 * APADW + 4];
            }
            #pragma unroll
            for (int nt = 0; nt < 4; nt++) {
                int c = wn + nt * 8 + gr;
                const uint32_t* p = Bhi + (bk2 + kq) * BPADW + c;
                const uint32_t* q = Blo + (bk2 + kq) * BPADW + c;
                bh[nt][0] = p[0];
                bh[nt][1] = p[4 * BPADW];
                bl[nt][0] = q[0];
                bl[nt][1] = q[4 * BPADW];
            }
            #pragma unroll
            for (int mt = 0; mt < 4; mt++)
                #pragma unroll
                for (int nt = 0; nt < 4; nt++) {
                    mma_bf16(acc[mt][nt], ah[mt], bh[nt]);
                    mma_bf16(acc[mt][nt], al[mt], bh[nt]);
                    mma_bf16(acc[mt][nt], ah[mt], bl[nt]);
                }
        }
    }
    __syncthreads();   // protect B region before next phase overwrites it
}

// ---------------- kernel 3: bf16 mma dual GEMM + fused BN stats ----------------
// gX = relu((agg@W) * norm_dst) + relu(X@Wres); accumulates g_sum/g_sumsq.
__global__ void __launch_bounds__(256, 1)
k_gemm_mma(const float* __restrict__ X, const float* __restrict__ W,
           const float* __restrict__ Wres) {
    extern __shared__ uint32_t smw[];
    const int tid = threadIdx.x;
    const int m0 = blockIdx.x * BM;
    const int lane = tid & 31, wid = tid >> 5;
    const int wm = (wid >> 2) * 64, wn = (wid & 3) * 32;
    const int gr = lane >> 2, kq = lane & 3;

    float acc[4][4][4];
    float keep[4][4][4];

    // ---- phase 1: residual X @ Wres ----
    #pragma unroll
    for (int mt = 0; mt < 4; mt++)
        #pragma unroll
        for (int nt = 0; nt < 4; nt++)
            #pragma unroll
            for (int q = 0; q < 4; q++) acc[mt][nt][q] = 0.f;
    run_phase(X, Wres, smw, m0, tid, acc);
    #pragma unroll
    for (int mt = 0; mt < 4; mt++)
        #pragma unroll
        for (int nt = 0; nt < 4; nt++)
            #pragma unroll
            for (int q = 0; q < 4; q++) {
                keep[mt][nt][q] = fmaxf(acc[mt][nt][q], 0.f);
                acc[mt][nt][q] = 0.f;
            }

    // ---- phase 2: conv agg @ W ----
    run_phase(g_agg, W, smw, m0, tid, acc);

    // ---- epilogue: combine, store, column stats ----
    float cs[8], cq[8];
    #pragma unroll
    for (int j = 0; j < 8; j++) { cs[j] = 0.f; cq[j] = 0.f; }

    #pragma unroll
    for (int mt = 0; mt < 4; mt++) {
        int r0 = m0 + wm + mt * 16 + gr;
        int r1 = r0 + 8;
        float s0 = (r0 < NODES) ? rsqrtf((float)max(g_degin[r0], 1)) : 0.f;
        float s1 = (r1 < NODES) ? rsqrtf((float)max(g_degin[r1], 1)) : 0.f;
        #pragma unroll
        for (int nt = 0; nt < 4; nt++) {
            float v0 = keep[mt][nt][0] + fmaxf(acc[mt][nt][0] * s0, 0.f);
            float v1 = keep[mt][nt][1] + fmaxf(acc[mt][nt][1] * s0, 0.f);
            float v2 = keep[mt][nt][2] + fmaxf(acc[mt][nt][2] * s1, 0.f);
            float v3 = keep[mt][nt][3] + fmaxf(acc[mt][nt][3] * s1, 0.f);
            int c = wn + nt * 8 + kq * 2;
            if (r0 < NODES) *(float2*)(g_gX + (size_t)r0 * DD + c) = make_float2(v0, v1);
            if (r1 < NODES) *(float2*)(g_gX + (size_t)r1 * DD + c) = make_float2(v2, v3);
            cs[2 * nt + 0] += v0 + v2;
            cs[2 * nt + 1] += v1 + v3;
            cq[2 * nt + 0] += v0 * v0 + v2 * v2;
            cq[2 * nt + 1] += v1 * v1 + v3 * v3;
        }
    }

    // reduce across the 8 lanes sharing each column (gr varies, kq fixed)
    #pragma unroll
    for (int j = 0; j < 8; j++) {
        #pragma unroll
        for (int off = 16; off >= 4; off >>= 1) {
            cs[j] += __shfl_xor_sync(0xFFFFFFFF, cs[j], off);
            cq[j] += __shfl_xor_sync(0xFFFFFFFF, cq[j], off);
        }
    }

    __syncthreads();
    float* redsum = (float*)smw;
    float* redsq  = (float*)smw + 128;
    if (tid < 128) { redsum[tid] = 0.f; redsq[tid] = 0.f; }
    __syncthreads();
    if (gr == 0) {  // one lane per (warp, kq)
        #pragma unroll
        for (int j = 0; j < 8; j++) {
            int c = wn + (j >> 1) * 8 + kq * 2 + (j & 1);
            atomicAdd(&redsum[c], cs[j]);
            atomicAdd(&redsq[c], cq[j]);
        }
    }
    __syncthreads();
    if (tid < 128) {
        atomicAdd(&g_sum[tid], redsum[tid]);
        atomicAdd(&g_sumsq[tid], redsq[tid]);
    }
}

// ---------------- kernel 4: finalize BN affine coefficients ----------------
__global__ void k_finalize(const float* __restrict__ gamma, const float* __restrict__ beta) {
    int c = threadIdx.x;
    const float invN = 1.f / (float)NODES;
    float mean = g_sum[c] * invN;
    float var  = fmaxf(g_sumsq[c] * invN - mean * mean, 0.f);
    float inv  = rsqrtf(var + BN_EPS);
    float s = gamma[c] * inv;
    g_scale[c] = s;
    g_bias[c]  = beta[c] - s * mean;
}

// ---------------- kernel 5: apply BN ----------------
__global__ void k_bn(float* __restrict__ out) {
    int i = blockIdx.x * blockDim.x + threadIdx.x;
    if (i >= NODES * DD / 4) return;
    int c4 = i & 31;
    float4 sc = ((const float4*)g_scale)[c4];
    float4 bi = ((const float4*)g_bias)[c4];
    float4 v  = ((const float4*)g_gX)[i];
    float4 o;
    o.x = fmaf(v.x, sc.x, bi.x);
    o.y = fmaf(v.y, sc.y, bi.y);
    o.z = fmaf(v.z, sc.z, bi.z);
    o.w = fmaf(v.w, sc.w, bi.w);
    ((float4*)out)[i] = o;
}

// ---------------- launch ----------------
extern "C" void kernel_launch(void* const* d_in, const int* in_sizes, int n_in,
                              void* d_out, int out_size) {
    const float* X     = (const float*)d_in[0];
    const float* W     = (const float*)d_in[1];
    const float* Wres  = (const float*)d_in[2];
    const float* gamma = (const float*)d_in[3];
    const float* beta  = (const float*)d_in[4];
    const int*   src   = (const int*)d_in[5];
    const int*   dst   = (const int*)d_in[6];
    float* out = (float*)d_out;

    (void)in_sizes; (void)n_in; (void)out_size;

    cudaFuncSetAttribute(k_gemm_mma, cudaFuncAttributeMaxDynamicSharedMemorySize, SMEM_BYTES);

    k_init<<<(NODES * DD / 4 + 255) / 256, 256>>>();
    k_deg<<<(NEDGES + 255) / 256, 256>>>(src, dst);
    k_scatter<<<(NEDGES * 32 + 255) / 256, 256>>>(X, src, dst);
    k_gemm_mma<<<(NODES + BM - 1) / BM, 256, SMEM_BYTES>>>(X, W, Wres);
    k_finalize<<<1, DD>>>(gamma, beta);
    k_bn<<<(NODES * DD / 4 + 255) / 256, 256>>>(out);
}